// round 2
// baseline (speedup 1.0000x reference)
#include <cuda_runtime.h>
#include <cstdint>

// Problem constants (match reference_code)
#define NN 100000      // input nodes
#define MM 100000      // output nodes
#define NNZ_C 3200000  // edges
#define BB 32          // batch

// Scratch: batch-contiguous transposed copies (12.8 MB each)
__device__ float g_xt[NN * BB];   // x_t[n][b]
__device__ float g_yt[MM * BB];   // y_t[m][b] accumulator

// ---------------------------------------------------------------------------
// Kernel 1: zero the accumulator (float4 grid-stride)
// ---------------------------------------------------------------------------
__global__ void zero_yt_kernel() {
    float4* p = reinterpret_cast<float4*>(g_yt);
    int total = (MM * BB) / 4;
    for (int i = blockIdx.x * blockDim.x + threadIdx.x; i < total;
         i += gridDim.x * blockDim.x) {
        p[i] = make_float4(0.f, 0.f, 0.f, 0.f);
    }
}

// ---------------------------------------------------------------------------
// Kernel 2: transpose x (B, N) -> x_t (N, B) via 32x32 smem tile
// blockDim = 1024 (32x32), gridDim.x = N/32
// ---------------------------------------------------------------------------
__global__ void transpose_in_kernel(const float* __restrict__ x) {
    __shared__ float tile[32][33];
    int n0 = blockIdx.x * 32;
    int tx = threadIdx.x & 31;   // inner
    int ty = threadIdx.x >> 5;   // outer
    // read: row ty = batch, col n0+tx  (coalesced along n)
    int n = n0 + tx;
    tile[ty][tx] = (n < NN) ? x[ty * NN + n] : 0.f;
    __syncthreads();
    // write: x_t[n0+ty][tx=b]  (coalesced along b)
    int n2 = n0 + ty;
    if (n2 < NN) g_xt[n2 * BB + tx] = tile[tx][ty];
}

// ---------------------------------------------------------------------------
// Kernel 3: edge scatter. Each warp owns 32 edges (coalesced edge loads),
// then processes 4 edges at a time: 8 lanes per edge, float4 per lane.
// gather: 128B line from x_t[src];  scatter: red.global.add.v4.f32 to y_t[dst]
// ---------------------------------------------------------------------------
__global__ void edge_kernel(const int* __restrict__ src,
                            const int* __restrict__ dst,
                            const float* __restrict__ vals) {
    int gtid = blockIdx.x * blockDim.x + threadIdx.x;
    int warp_id = gtid >> 5;
    int lane = threadIdx.x & 31;

    int e0 = warp_id * 32;
    if (e0 >= NNZ_C) return;

    int e = e0 + lane;
    bool ok = (e < NNZ_C);
    int   s = ok ? src[e]  : 0;
    int   d = ok ? dst[e]  : -1;
    float v = ok ? vals[e] : 0.f;

    int seg = lane & 7;   // which float4 of the 32-float row
    int sub = lane >> 3;  // which of 4 concurrent edges

    const float4* xt4 = reinterpret_cast<const float4*>(g_xt);

#pragma unroll
    for (int j = 0; j < 8; j++) {
        int eidx = j * 4 + sub;
        int   se = __shfl_sync(0xffffffffu, s, eidx);
        int   de = __shfl_sync(0xffffffffu, d, eidx);
        float ve = __shfl_sync(0xffffffffu, v, eidx);
        if (de >= 0) {
            float4 xv = __ldg(&xt4[se * 8 + seg]);
            float cx = xv.x * ve, cy = xv.y * ve, cz = xv.z * ve, cw = xv.w * ve;
            float* p = g_yt + de * BB + seg * 4;
            asm volatile(
                "red.global.add.v4.f32 [%0], {%1, %2, %3, %4};"
                :: "l"(p), "f"(cx), "f"(cy), "f"(cz), "f"(cw)
                : "memory");
        }
    }
}

// ---------------------------------------------------------------------------
// Kernel 4: out (B, M) = transpose(y_t (M, B)) + bias
// blockDim = 1024 (32x32), gridDim.x = M/32
// ---------------------------------------------------------------------------
__global__ void transpose_out_kernel(float* __restrict__ out,
                                     const float* __restrict__ bias) {
    __shared__ float tile[32][33];
    int m0 = blockIdx.x * 32;
    int tx = threadIdx.x & 31;
    int ty = threadIdx.x >> 5;
    // read: y_t[m0+ty][tx=b] coalesced along b; add bias[m]
    int m = m0 + ty;
    if (m < MM) tile[ty][tx] = g_yt[m * BB + tx] + bias[m];
    __syncthreads();
    // write: out[b=ty][m0+tx] coalesced along m
    int m2 = m0 + tx;
    if (m2 < MM) out[ty * MM + m2] = tile[tx][ty];
}

// ---------------------------------------------------------------------------
extern "C" void kernel_launch(void* const* d_in, const int* in_sizes, int n_in,
                              void* d_out, int out_size) {
    const float* x       = (const float*)d_in[0];   // (B, N, 1)
    const int*   indices = (const int*)d_in[1];     // (2, NNZ)
    const float* vals    = (const float*)d_in[2];   // (NNZ,)
    const float* bias    = (const float*)d_in[3];   // (M, 1)
    float* out = (float*)d_out;                     // (B, M, 1)

    const int* src = indices;
    const int* dst = indices + NNZ_C;

    // 1) zero accumulator
    zero_yt_kernel<<<512, 256>>>();

    // 2) transpose x -> x_t
    transpose_in_kernel<<<(NN + 31) / 32, 1024>>>(x);

    // 3) edge scatter (one warp per 32 edges)
    {
        int warps = (NNZ_C + 31) / 32;
        int threads = warps * 32;
        int block = 256;
        int grid = (threads + block - 1) / block;
        edge_kernel<<<grid, block>>>(src, dst, vals);
    }

    // 4) transpose back + bias
    transpose_out_kernel<<<(MM + 31) / 32, 1024>>>(out, bias);
}